// round 1
// baseline (speedup 1.0000x reference)
#include <cuda_runtime.h>
#include <cuda_bf16.h>
#include <math.h>

// Problem constants
#define BATCH 2
#define SEQ 2048
#define DM 1024
#define NH 16
#define DH 64
#define MROWS (BATCH * SEQ)   // 4096

// ---------------------------------------------------------------------------
// Scratch (no cudaMalloc allowed): Q, K, V projections + attention context
// ---------------------------------------------------------------------------
__device__ float g_Q[MROWS * DM];
__device__ float g_K[MROWS * DM];
__device__ float g_V[MROWS * DM];
__device__ float g_C[MROWS * DM];

// ---------------------------------------------------------------------------
// GEMM: C[M,N] = A[M,K] * W[N,K]^T + bias[N]
// BM=BN=128, BK=16, 256 threads, 8x8 per thread
// ---------------------------------------------------------------------------
#define GBM 128
#define GBN 128
#define GBK 16
#define GTM 8
#define GTN 8

__global__ __launch_bounds__(256) void gemm_bias_kernel(
    const float* __restrict__ A, const float* __restrict__ W,
    const float* __restrict__ bias, float* __restrict__ C,
    int M, int N, int K)
{
    __shared__ float As[GBK][GBM];
    __shared__ float Ws[GBK][GBN];

    const int tid  = threadIdx.x;
    const int brow = blockIdx.y;
    const int bcol = blockIdx.x;

    const float* Ab = A + (long)brow * GBM * K;
    const float* Wb = W + (long)bcol * GBN * K;

    const int lrow  = tid >> 2;         // 0..63
    const int lcol4 = (tid & 3) << 2;   // 0,4,8,12

    const int tr = tid >> 4;            // 0..15
    const int tc = tid & 15;            // 0..15

    float acc[GTM][GTN];
    #pragma unroll
    for (int i = 0; i < GTM; i++)
        #pragma unroll
        for (int j = 0; j < GTN; j++) acc[i][j] = 0.0f;

    for (int kt = 0; kt < K; kt += GBK) {
        // Load A tile (transposed into shared)
        #pragma unroll
        for (int r = 0; r < GBM; r += 64) {
            float4 v = *(const float4*)(Ab + (long)(lrow + r) * K + kt + lcol4);
            As[lcol4 + 0][lrow + r] = v.x;
            As[lcol4 + 1][lrow + r] = v.y;
            As[lcol4 + 2][lrow + r] = v.z;
            As[lcol4 + 3][lrow + r] = v.w;
        }
        // Load W tile (transposed into shared)
        #pragma unroll
        for (int r = 0; r < GBN; r += 64) {
            float4 v = *(const float4*)(Wb + (long)(lrow + r) * K + kt + lcol4);
            Ws[lcol4 + 0][lrow + r] = v.x;
            Ws[lcol4 + 1][lrow + r] = v.y;
            Ws[lcol4 + 2][lrow + r] = v.z;
            Ws[lcol4 + 3][lrow + r] = v.w;
        }
        __syncthreads();

        #pragma unroll
        for (int k = 0; k < GBK; k++) {
            float ra[GTM], rb[GTN];
            #pragma unroll
            for (int i = 0; i < GTM; i++) ra[i] = As[k][tr * GTM + i];
            #pragma unroll
            for (int j = 0; j < GTN; j++) rb[j] = Ws[k][tc * GTN + j];
            #pragma unroll
            for (int i = 0; i < GTM; i++)
                #pragma unroll
                for (int j = 0; j < GTN; j++)
                    acc[i][j] = fmaf(ra[i], rb[j], acc[i][j]);
        }
        __syncthreads();
    }

    #pragma unroll
    for (int i = 0; i < GTM; i++) {
        int row = brow * GBM + tr * GTM + i;
        #pragma unroll
        for (int j = 0; j < GTN; j++) {
            int col = bcol * GBN + tc * GTN + j;
            C[(long)row * N + col] = acc[i][j] + bias[col];
        }
    }
}

// ---------------------------------------------------------------------------
// Flash attention: one block per (bh, 64-query tile).
// Q/K/V stored as [B,S,DM] with head h at columns h*64..h*64+63.
// 256 threads: (tr,tc) 16x16; each thread: 4 q-rows x 4 cols.
// Dynamic smem: Qs[64*64] + Ks[64*65] + Vs[64*65] + Ps[64*64] = 66048 B
// ---------------------------------------------------------------------------
#define ATT_SMEM_BYTES ((4096 + 64*65 + 64*65 + 4096) * 4)

__global__ __launch_bounds__(256) void attn_kernel(
    const float* __restrict__ Q, const float* __restrict__ K,
    const float* __restrict__ V, float* __restrict__ Ctx)
{
    extern __shared__ float sm[];
    float* Qs = sm;                 // [64][64]
    float* Ks = Qs + 64 * 64;       // [64][65]
    float* Vs = Ks + 64 * 65;       // [64][65]
    float* Ps = Vs + 64 * 65;       // [64][64]

    const int bh = blockIdx.y;          // 0..31
    const int b  = bh >> 4;
    const int h  = bh & 15;
    const int q0 = blockIdx.x * 64;

    const int tid = threadIdx.x;
    const int tr  = tid >> 4;   // 0..15
    const int tc  = tid & 15;   // 0..15

    const float* Qg = Q + ((long)b * SEQ) * DM + h * DH;
    const float* Kg = K + ((long)b * SEQ) * DM + h * DH;
    const float* Vg = V + ((long)b * SEQ) * DM + h * DH;

    // Load Q tile (64 rows x 64 cols), float4 both ways (Qs unpadded)
    #pragma unroll
    for (int p = 0; p < 4; p++) {
        int row = tr + 16 * p;
        float4 v = *(const float4*)(Qg + (long)(q0 + row) * DM + tc * 4);
        *(float4*)(Qs + row * 64 + tc * 4) = v;
    }

    float o[4][4];
    float mrun[4], lrun[4];
    #pragma unroll
    for (int i = 0; i < 4; i++) {
        mrun[i] = -INFINITY;
        lrun[i] = 0.0f;
        #pragma unroll
        for (int j = 0; j < 4; j++) o[i][j] = 0.0f;
    }

    const float scale = 0.125f;  // 1/sqrt(64)

    for (int t = 0; t < SEQ; t += 64) {
        __syncthreads();  // prior PV / Q-load done before overwriting K/V

        // Load K & V tiles into padded shared (float4 gmem read, scalar STS)
        #pragma unroll
        for (int p = 0; p < 4; p++) {
            int row = tr + 16 * p;
            float4 kv = *(const float4*)(Kg + (long)(t + row) * DM + tc * 4);
            Ks[row * 65 + tc * 4 + 0] = kv.x;
            Ks[row * 65 + tc * 4 + 1] = kv.y;
            Ks[row * 65 + tc * 4 + 2] = kv.z;
            Ks[row * 65 + tc * 4 + 3] = kv.w;
            float4 vv = *(const float4*)(Vg + (long)(t + row) * DM + tc * 4);
            Vs[row * 65 + tc * 4 + 0] = vv.x;
            Vs[row * 65 + tc * 4 + 1] = vv.y;
            Vs[row * 65 + tc * 4 + 2] = vv.z;
            Vs[row * 65 + tc * 4 + 3] = vv.w;
        }
        __syncthreads();

        // S = Q * K^T (per-thread 4x4)
        float s[4][4];
        #pragma unroll
        for (int i = 0; i < 4; i++)
            #pragma unroll
            for (int j = 0; j < 4; j++) s[i][j] = 0.0f;

        #pragma unroll 16
        for (int d = 0; d < 64; d++) {
            float qv[4], kv[4];
            #pragma unroll
            for (int i = 0; i < 4; i++) qv[i] = Qs[(tr * 4 + i) * 64 + d];
            #pragma unroll
            for (int j = 0; j < 4; j++) kv[j] = Ks[(tc * 4 + j) * 65 + d];
            #pragma unroll
            for (int i = 0; i < 4; i++)
                #pragma unroll
                for (int j = 0; j < 4; j++)
                    s[i][j] = fmaf(qv[i], kv[j], s[i][j]);
        }

        // Online softmax per q-row (reduce across the 16 tc lanes)
        #pragma unroll
        for (int i = 0; i < 4; i++) {
            #pragma unroll
            for (int j = 0; j < 4; j++) s[i][j] *= scale;

            float mt = fmaxf(fmaxf(s[i][0], s[i][1]), fmaxf(s[i][2], s[i][3]));
            #pragma unroll
            for (int off = 8; off >= 1; off >>= 1)
                mt = fmaxf(mt, __shfl_xor_sync(0xffffffffu, mt, off));

            float mnew  = fmaxf(mrun[i], mt);
            float alpha = __expf(mrun[i] - mnew);
            mrun[i] = mnew;

            float rs = 0.0f;
            #pragma unroll
            for (int j = 0; j < 4; j++) {
                s[i][j] = __expf(s[i][j] - mnew);
                rs += s[i][j];
            }
            #pragma unroll
            for (int off = 8; off >= 1; off >>= 1)
                rs += __shfl_xor_sync(0xffffffffu, rs, off);

            lrun[i] = lrun[i] * alpha + rs;
            #pragma unroll
            for (int j = 0; j < 4; j++) o[i][j] *= alpha;

            // Stage P for the PV GEMM
            #pragma unroll
            for (int j = 0; j < 4; j++)
                Ps[(tr * 4 + i) * 64 + tc * 4 + j] = s[i][j];
        }
        __syncthreads();

        // O += P * V   (P: q-rows x 64 keys, V: 64 keys x 64 dh-cols)
        #pragma unroll 16
        for (int kk = 0; kk < 64; kk++) {
            float pv[4], vv[4];
            #pragma unroll
            for (int i = 0; i < 4; i++) pv[i] = Ps[(tr * 4 + i) * 64 + kk];
            #pragma unroll
            for (int j = 0; j < 4; j++) vv[j] = Vs[kk * 65 + tc * 4 + j];
            #pragma unroll
            for (int i = 0; i < 4; i++)
                #pragma unroll
                for (int j = 0; j < 4; j++)
                    o[i][j] = fmaf(pv[i], vv[j], o[i][j]);
        }
    }

    // Normalize + write context (merged heads layout [B,S,DM])
    #pragma unroll
    for (int i = 0; i < 4; i++) {
        float inv = 1.0f / lrun[i];
        int row = q0 + tr * 4 + i;
        #pragma unroll
        for (int j = 0; j < 4; j++) {
            Ctx[((long)b * SEQ + row) * DM + h * DH + tc * 4 + j] = o[i][j] * inv;
        }
    }
}

// ---------------------------------------------------------------------------
// kernel_launch
// Inputs (metadata order): q,k,v, Wq,bq, Wk,bk, Wv,bv, Wo,bo
// ---------------------------------------------------------------------------
extern "C" void kernel_launch(void* const* d_in, const int* in_sizes, int n_in,
                              void* d_out, int out_size)
{
    const float* q  = (const float*)d_in[0];
    const float* k  = (const float*)d_in[1];
    const float* v  = (const float*)d_in[2];
    const float* Wq = (const float*)d_in[3];
    const float* bq = (const float*)d_in[4];
    const float* Wk = (const float*)d_in[5];
    const float* bk = (const float*)d_in[6];
    const float* Wv = (const float*)d_in[7];
    const float* bv = (const float*)d_in[8];
    const float* Wo = (const float*)d_in[9];
    const float* bo = (const float*)d_in[10];
    float* out = (float*)d_out;

    float *pQ, *pK, *pV, *pC;
    cudaGetSymbolAddress((void**)&pQ, g_Q);
    cudaGetSymbolAddress((void**)&pK, g_K);
    cudaGetSymbolAddress((void**)&pV, g_V);
    cudaGetSymbolAddress((void**)&pC, g_C);

    cudaFuncSetAttribute(attn_kernel,
                         cudaFuncAttributeMaxDynamicSharedMemorySize,
                         ATT_SMEM_BYTES);

    dim3 ggrid(DM / GBN, MROWS / GBM);   // (8, 32)
    gemm_bias_kernel<<<ggrid, 256>>>(q, Wq, bq, pQ, MROWS, DM, DM);
    gemm_bias_kernel<<<ggrid, 256>>>(k, Wk, bk, pK, MROWS, DM, DM);
    gemm_bias_kernel<<<ggrid, 256>>>(v, Wv, bv, pV, MROWS, DM, DM);

    dim3 agrid(SEQ / 64, BATCH * NH);    // (32, 32)
    attn_kernel<<<agrid, 256, ATT_SMEM_BYTES>>>(pQ, pK, pV, pC);

    gemm_bias_kernel<<<ggrid, 256>>>(pC, Wo, bo, out, MROWS, DM, DM);
}

// round 4
// speedup vs baseline: 1.5754x; 1.5754x over previous
#include <cuda_runtime.h>
#include <cuda_bf16.h>
#include <math.h>
#include <cstdint>

// Problem constants
#define BATCH 2
#define SEQ 2048
#define DM 1024
#define NH 16
#define DH 64
#define MROWS (BATCH * SEQ)   // 4096

// ---------------------------------------------------------------------------
// Scratch (no cudaMalloc allowed)
// ---------------------------------------------------------------------------
__device__ float g_Q[MROWS * DM];
__device__ float g_K[MROWS * DM];
__device__ float g_V[MROWS * DM];
__device__ float g_C[MROWS * DM];

// ---------------------------------------------------------------------------
// tf32 mma.sync GEMM: C[M,N] = A[M,K] * W[N,K]^T + bias[N]
// Tile 128x128x32, 256 threads = 8 warps (2 x 4), warp tile 64x32.
// mma.sync.m16n8k8.row.col.f32.tf32.tf32.f32 (base ISA, lowers to HMMA).
// ---------------------------------------------------------------------------
#define BM 128
#define BN 128
#define BK 32
#define KPAD 36          // smem row stride (floats): 4*gid+tig mod 32 unique
#define NCHUNK (DM / BK) // 32

__device__ __forceinline__ void mma_tf32(float& c0, float& c1, float& c2, float& c3,
                                         uint32_t a0, uint32_t a1, uint32_t a2, uint32_t a3,
                                         uint32_t b0, uint32_t b1) {
    asm volatile(
        "mma.sync.aligned.m16n8k8.row.col.f32.tf32.tf32.f32 "
        "{%0,%1,%2,%3}, {%4,%5,%6,%7}, {%8,%9}, {%0,%1,%2,%3};"
        : "+f"(c0), "+f"(c1), "+f"(c2), "+f"(c3)
        : "r"(a0), "r"(a1), "r"(a2), "r"(a3), "r"(b0), "r"(b1));
}

// fp32 -> tf32 round-to-nearest via bit trick (HW mma truncates; +0x1000
// completes RN on the surviving 10 mantissa bits). Zero-mean error.
__device__ __forceinline__ uint32_t rnd_tf32(uint32_t x) { return x + 0x1000u; }

__global__ __launch_bounds__(256) void gemm_tf32_kernel(
    const float* __restrict__ A, const float* __restrict__ W,
    const float* __restrict__ bias, float* __restrict__ C)
{
    __shared__ uint32_t As[BM * KPAD];
    __shared__ uint32_t Bs[BN * KPAD];

    const int tid = threadIdx.x;
    const int wid = tid >> 5;
    const int lane = tid & 31;
    const int gid = lane >> 2;   // 0..7
    const int tig = lane & 3;    // 0..3

    const int wm = wid >> 2;     // 0..1  (m offset wm*64)
    const int wn = wid & 3;      // 0..3  (n offset wn*32)

    const int m0 = blockIdx.y * BM;
    const int n0 = blockIdx.x * BN;

    // global->reg staging: 4 float4 per matrix per thread per chunk
    // idx = tid + i*256 ; row = idx>>3 (0..127), c4 = (idx&7)*4
    const int grow = tid >> 3;
    const int gcol = (tid & 7) * 4;

    const uint4* Ag = (const uint4*)(A + (long)(m0 + grow) * DM + gcol);
    const uint4* Wg = (const uint4*)(W + (long)(n0 + grow) * DM + gcol);

    float acc[4][4][4];   // [mt][nt][c0..c3]
    #pragma unroll
    for (int i = 0; i < 4; i++)
        #pragma unroll
        for (int j = 0; j < 4; j++)
            #pragma unroll
            for (int c = 0; c < 4; c++) acc[i][j][c] = 0.0f;

    uint4 ra[4], rb[4];
    // prologue: load chunk 0 (each i covers 32 rows: rows grow + i*32)
    #pragma unroll
    for (int i = 0; i < 4; i++) {
        ra[i] = Ag[(long)i * 32 * (DM / 4)];
        rb[i] = Wg[(long)i * 32 * (DM / 4)];
    }

    for (int c = 0; c < NCHUNK; c++) {
        // store staged chunk to smem with tf32 RN rounding
        #pragma unroll
        for (int i = 0; i < 4; i++) {
            uint32_t* as = &As[(grow + i * 32) * KPAD + gcol];
            as[0] = rnd_tf32(ra[i].x); as[1] = rnd_tf32(ra[i].y);
            as[2] = rnd_tf32(ra[i].z); as[3] = rnd_tf32(ra[i].w);
            uint32_t* bs = &Bs[(grow + i * 32) * KPAD + gcol];
            bs[0] = rnd_tf32(rb[i].x); bs[1] = rnd_tf32(rb[i].y);
            bs[2] = rnd_tf32(rb[i].z); bs[3] = rnd_tf32(rb[i].w);
        }
        __syncthreads();

        // prefetch next chunk while mma consumes smem
        if (c + 1 < NCHUNK) {
            const uint4* an = Ag + (long)(c + 1) * (BK / 4);
            const uint4* bn = Wg + (long)(c + 1) * (BK / 4);
            #pragma unroll
            for (int i = 0; i < 4; i++) {
                ra[i] = an[(long)i * 32 * (DM / 4)];
                rb[i] = bn[(long)i * 32 * (DM / 4)];
            }
        }

        // 4 k-steps of k=8
        #pragma unroll
        for (int ks = 0; ks < 4; ks++) {
            const int k0 = ks * 8;
            uint32_t af[4][4], bf[4][2];
            #pragma unroll
            for (int mt = 0; mt < 4; mt++) {
                const int r = wm * 64 + mt * 16 + gid;
                af[mt][0] = As[r * KPAD + k0 + tig];
                af[mt][1] = As[(r + 8) * KPAD + k0 + tig];
                af[mt][2] = As[r * KPAD + k0 + tig + 4];
                af[mt][3] = As[(r + 8) * KPAD + k0 + tig + 4];
            }
            #pragma unroll
            for (int nt = 0; nt < 4; nt++) {
                const int r = wn * 32 + nt * 8 + gid;
                bf[nt][0] = Bs[r * KPAD + k0 + tig];
                bf[nt][1] = Bs[r * KPAD + k0 + tig + 4];
            }
            #pragma unroll
            for (int mt = 0; mt < 4; mt++)
                #pragma unroll
                for (int nt = 0; nt < 4; nt++)
                    mma_tf32(acc[mt][nt][0], acc[mt][nt][1],
                             acc[mt][nt][2], acc[mt][nt][3],
                             af[mt][0], af[mt][1], af[mt][2], af[mt][3],
                             bf[nt][0], bf[nt][1]);
        }
        __syncthreads();
    }

    // epilogue: c0: (gid, 2tig) c1: (gid, 2tig+1) c2: (gid+8, 2tig) c3: (gid+8, 2tig+1)
    #pragma unroll
    for (int mt = 0; mt < 4; mt++) {
        const int mrow = m0 + wm * 64 + mt * 16 + gid;
        #pragma unroll
        for (int nt = 0; nt < 4; nt++) {
            const int ncol = n0 + wn * 32 + nt * 8 + tig * 2;
            const float bx = bias[ncol];
            const float by = bias[ncol + 1];
            float2 v0 = make_float2(acc[mt][nt][0] + bx, acc[mt][nt][1] + by);
            float2 v1 = make_float2(acc[mt][nt][2] + bx, acc[mt][nt][3] + by);
            *(float2*)(C + (long)mrow * DM + ncol) = v0;
            *(float2*)(C + (long)(mrow + 8) * DM + ncol) = v1;
        }
    }
}

// ---------------------------------------------------------------------------
// Flash attention (fp32, unchanged — at FFMA roofline)
// ---------------------------------------------------------------------------
#define ATT_SMEM_BYTES ((4096 + 64*65 + 64*65 + 4096) * 4)

__global__ __launch_bounds__(256) void attn_kernel(
    const float* __restrict__ Q, const float* __restrict__ K,
    const float* __restrict__ V, float* __restrict__ Ctx)
{
    extern __shared__ float sm[];
    float* Qs = sm;                 // [64][64]
    float* Ks = Qs + 64 * 64;       // [64][65]
    float* Vs = Ks + 64 * 65;       // [64][65]
    float* Ps = Vs + 64 * 65;       // [64][64]

    const int bh = blockIdx.y;
    const int b  = bh >> 4;
    const int h  = bh & 15;
    const int q0 = blockIdx.x * 64;

    const int tid = threadIdx.x;
    const int tr  = tid >> 4;
    const int tc  = tid & 15;

    const float* Qg = Q + ((long)b * SEQ) * DM + h * DH;
    const float* Kg = K + ((long)b * SEQ) * DM + h * DH;
    const float* Vg = V + ((long)b * SEQ) * DM + h * DH;

    #pragma unroll
    for (int p = 0; p < 4; p++) {
        int row = tr + 16 * p;
        float4 v = *(const float4*)(Qg + (long)(q0 + row) * DM + tc * 4);
        *(float4*)(Qs + row * 64 + tc * 4) = v;
    }

    float o[4][4];
    float mrun[4], lrun[4];
    #pragma unroll
    for (int i = 0; i < 4; i++) {
        mrun[i] = -INFINITY;
        lrun[i] = 0.0f;
        #pragma unroll
        for (int j = 0; j < 4; j++) o[i][j] = 0.0f;
    }

    const float scale = 0.125f;

    for (int t = 0; t < SEQ; t += 64) {
        __syncthreads();

        #pragma unroll
        for (int p = 0; p < 4; p++) {
            int row = tr + 16 * p;
            float4 kv = *(const float4*)(Kg + (long)(t + row) * DM + tc * 4);
            Ks[row * 65 + tc * 4 + 0] = kv.x;
            Ks[row * 65 + tc * 4 + 1] = kv.y;
            Ks[row * 65 + tc * 4 + 2] = kv.z;
            Ks[row * 65 + tc * 4 + 3] = kv.w;
            float4 vv = *(const float4*)(Vg + (long)(t + row) * DM + tc * 4);
            Vs[row * 65 + tc * 4 + 0] = vv.x;
            Vs[row * 65 + tc * 4 + 1] = vv.y;
            Vs[row * 65 + tc * 4 + 2] = vv.z;
            Vs[row * 65 + tc * 4 + 3] = vv.w;
        }
        __syncthreads();

        float s[4][4];
        #pragma unroll
        for (int i = 0; i < 4; i++)
            #pragma unroll
            for (int j = 0; j < 4; j++) s[i][j] = 0.0f;

        #pragma unroll 16
        for (int d = 0; d < 64; d++) {
            float qv[4], kv[4];
            #pragma unroll
            for (int i = 0; i < 4; i++) qv[i] = Qs[(tr * 4 + i) * 64 + d];
            #pragma unroll
            for (int j = 0; j < 4; j++) kv[j] = Ks[(tc * 4 + j) * 65 + d];
            #pragma unroll
            for (int i = 0; i < 4; i++)
                #pragma unroll
                for (int j = 0; j < 4; j++)
                    s[i][j] = fmaf(qv[i], kv[j], s[i][j]);
        }

        #pragma unroll
        for (int i = 0; i < 4; i++) {
            #pragma unroll
            for (int j = 0; j < 4; j++) s[i][j] *= scale;

            float mt = fmaxf(fmaxf(s[i][0], s[i][1]), fmaxf(s[i][2], s[i][3]));
            #pragma unroll
            for (int off = 8; off >= 1; off >>= 1)
                mt = fmaxf(mt, __shfl_xor_sync(0xffffffffu, mt, off));

            float mnew  = fmaxf(mrun[i], mt);
            float alpha = __expf(mrun[i] - mnew);
            mrun[i] = mnew;

            float rs = 0.0f;
            #pragma unroll
            for (int j = 0; j < 4; j++) {
                s[i][j] = __expf(s[i][j] - mnew);
                rs += s[i][j];
            }
            #pragma unroll
            for (int off = 8; off >= 1; off >>= 1)
                rs += __shfl_xor_sync(0xffffffffu, rs, off);

            lrun[i] = lrun[i] * alpha + rs;
            #pragma unroll
            for (int j = 0; j < 4; j++) o[i][j] *= alpha;

            #pragma unroll
            for (int j = 0; j < 4; j++)
                Ps[(tr * 4 + i) * 64 + tc * 4 + j] = s[i][j];
        }
        __syncthreads();

        #pragma unroll 16
        for (int kk = 0; kk < 64; kk++) {
            float pv[4], vv[4];
            #pragma unroll
            for (int i = 0; i < 4; i++) pv[i] = Ps[(tr * 4 + i) * 64 + kk];
            #pragma unroll
            for (int j = 0; j < 4; j++) vv[j] = Vs[kk * 65 + tc * 4 + j];
            #pragma unroll
            for (int i = 0; i < 4; i++)
                #pragma unroll
                for (int j = 0; j < 4; j++)
                    o[i][j] = fmaf(pv[i], vv[j], o[i][j]);
        }
    }

    #pragma unroll
    for (int i = 0; i < 4; i++) {
        float inv = 1.0f / lrun[i];
        int row = q0 + tr * 4 + i;
        #pragma unroll
        for (int j = 0; j < 4; j++) {
            Ctx[((long)b * SEQ + row) * DM + h * DH + tc * 4 + j] = o[i][j] * inv;
        }
    }
}

// ---------------------------------------------------------------------------
// kernel_launch  — inputs: q,k,v, Wq,bq, Wk,bk, Wv,bv, Wo,bo
// ---------------------------------------------------------------------------
extern "C" void kernel_launch(void* const* d_in, const int* in_sizes, int n_in,
                              void* d_out, int out_size)
{
    const float* q  = (const float*)d_in[0];
    const float* k  = (const float*)d_in[1];
    const float* v  = (const float*)d_in[2];
    const float* Wq = (const float*)d_in[3];
    const float* bq = (const float*)d_in[4];
    const float* Wk = (const float*)d_in[5];
    const float* bk = (const float*)d_in[6];
    const float* Wv = (const float*)d_in[7];
    const float* bv = (const float*)d_in[8];
    const float* Wo = (const float*)d_in[9];
    const float* bo = (const float*)d_in[10];
    float* out = (float*)d_out;

    float *pQ, *pK, *pV, *pC;
    cudaGetSymbolAddress((void**)&pQ, g_Q);
    cudaGetSymbolAddress((void**)&pK, g_K);
    cudaGetSymbolAddress((void**)&pV, g_V);
    cudaGetSymbolAddress((void**)&pC, g_C);

    cudaFuncSetAttribute(attn_kernel,
                         cudaFuncAttributeMaxDynamicSharedMemorySize,
                         ATT_SMEM_BYTES);

    dim3 ggrid(DM / BN, MROWS / BM);     // (8, 32)
    gemm_tf32_kernel<<<ggrid, 256>>>(q, Wq, bq, pQ);
    gemm_tf32_kernel<<<ggrid, 256>>>(k, Wk, bk, pK);
    gemm_tf32_kernel<<<ggrid, 256>>>(v, Wv, bv, pV);

    dim3 agrid(SEQ / 64, BATCH * NH);    // (32, 32)
    attn_kernel<<<agrid, 256, ATT_SMEM_BYTES>>>(pQ, pK, pV, pC);

    gemm_tf32_kernel<<<ggrid, 256>>>(pC, Wo, bo, out);
}

// round 6
// speedup vs baseline: 3.1725x; 2.0138x over previous
#include <cuda_runtime.h>
#include <cuda_bf16.h>
#include <math.h>
#include <cstdint>

// Problem constants
#define BATCH 2
#define SEQ 2048
#define DM 1024
#define NH 16
#define DH 64
#define MROWS (BATCH * SEQ)   // 4096

// ---------------------------------------------------------------------------
// Scratch (no cudaMalloc allowed)
// ---------------------------------------------------------------------------
__device__ float g_Q[MROWS * DM];
__device__ float g_K[MROWS * DM];
__device__ float g_V[MROWS * DM];
__device__ float g_C[MROWS * DM];

// ---------------------------------------------------------------------------
// Common helpers
// ---------------------------------------------------------------------------
__device__ __forceinline__ void mma_tf32(float& c0, float& c1, float& c2, float& c3,
                                         uint32_t a0, uint32_t a1, uint32_t a2, uint32_t a3,
                                         uint32_t b0, uint32_t b1) {
    asm volatile(
        "mma.sync.aligned.m16n8k8.row.col.f32.tf32.tf32.f32 "
        "{%0,%1,%2,%3}, {%4,%5,%6,%7}, {%8,%9}, {%0,%1,%2,%3};"
        : "+f"(c0), "+f"(c1), "+f"(c2), "+f"(c3)
        : "r"(a0), "r"(a1), "r"(a2), "r"(a3), "r"(b0), "r"(b1));
}

// fp32 -> tf32 round-to-nearest bit trick (HW truncates; +0x1000 completes RN)
__device__ __forceinline__ uint32_t rnd_tf32(uint32_t x) { return x + 0x1000u; }
__device__ __forceinline__ uint32_t rnd_tf32f(float x) { return __float_as_uint(x) + 0x1000u; }

__device__ __forceinline__ float ex2f(float x) {
    float y;
    asm("ex2.approx.f32 %0, %1;" : "=f"(y) : "f"(x));
    return y;
}

// ---------------------------------------------------------------------------
// tf32 mma.sync GEMM: C[M,N] = A[M,K] * W[N,K]^T + bias[N]  (unchanged, R4)
// ---------------------------------------------------------------------------
#define BM 128
#define BN 128
#define BK 32
#define KPAD 36
#define NCHUNK (DM / BK)

__global__ __launch_bounds__(256) void gemm_tf32_kernel(
    const float* __restrict__ A, const float* __restrict__ W,
    const float* __restrict__ bias, float* __restrict__ C)
{
    __shared__ uint32_t As[BM * KPAD];
    __shared__ uint32_t Bs[BN * KPAD];

    const int tid = threadIdx.x;
    const int wid = tid >> 5;
    const int lane = tid & 31;
    const int gid = lane >> 2;
    const int tig = lane & 3;

    const int wm = wid >> 2;
    const int wn = wid & 3;

    const int m0 = blockIdx.y * BM;
    const int n0 = blockIdx.x * BN;

    const int grow = tid >> 3;
    const int gcol = (tid & 7) * 4;

    const uint4* Ag = (const uint4*)(A + (long)(m0 + grow) * DM + gcol);
    const uint4* Wg = (const uint4*)(W + (long)(n0 + grow) * DM + gcol);

    float acc[4][4][4];
    #pragma unroll
    for (int i = 0; i < 4; i++)
        #pragma unroll
        for (int j = 0; j < 4; j++)
            #pragma unroll
            for (int c = 0; c < 4; c++) acc[i][j][c] = 0.0f;

    uint4 ra[4], rb[4];
    #pragma unroll
    for (int i = 0; i < 4; i++) {
        ra[i] = Ag[(long)i * 32 * (DM / 4)];
        rb[i] = Wg[(long)i * 32 * (DM / 4)];
    }

    for (int c = 0; c < NCHUNK; c++) {
        #pragma unroll
        for (int i = 0; i < 4; i++) {
            uint32_t* as = &As[(grow + i * 32) * KPAD + gcol];
            as[0] = rnd_tf32(ra[i].x); as[1] = rnd_tf32(ra[i].y);
            as[2] = rnd_tf32(ra[i].z); as[3] = rnd_tf32(ra[i].w);
            uint32_t* bs = &Bs[(grow + i * 32) * KPAD + gcol];
            bs[0] = rnd_tf32(rb[i].x); bs[1] = rnd_tf32(rb[i].y);
            bs[2] = rnd_tf32(rb[i].z); bs[3] = rnd_tf32(rb[i].w);
        }
        __syncthreads();

        if (c + 1 < NCHUNK) {
            const uint4* an = Ag + (long)(c + 1) * (BK / 4);
            const uint4* bn = Wg + (long)(c + 1) * (BK / 4);
            #pragma unroll
            for (int i = 0; i < 4; i++) {
                ra[i] = an[(long)i * 32 * (DM / 4)];
                rb[i] = bn[(long)i * 32 * (DM / 4)];
            }
        }

        #pragma unroll
        for (int ks = 0; ks < 4; ks++) {
            const int k0 = ks * 8;
            uint32_t af[4][4], bf[4][2];
            #pragma unroll
            for (int mt = 0; mt < 4; mt++) {
                const int r = wm * 64 + mt * 16 + gid;
                af[mt][0] = As[r * KPAD + k0 + tig];
                af[mt][1] = As[(r + 8) * KPAD + k0 + tig];
                af[mt][2] = As[r * KPAD + k0 + tig + 4];
                af[mt][3] = As[(r + 8) * KPAD + k0 + tig + 4];
            }
            #pragma unroll
            for (int nt = 0; nt < 4; nt++) {
                const int r = wn * 32 + nt * 8 + gid;
                bf[nt][0] = Bs[r * KPAD + k0 + tig];
                bf[nt][1] = Bs[r * KPAD + k0 + tig + 4];
            }
            #pragma unroll
            for (int mt = 0; mt < 4; mt++)
                #pragma unroll
                for (int nt = 0; nt < 4; nt++)
                    mma_tf32(acc[mt][nt][0], acc[mt][nt][1],
                             acc[mt][nt][2], acc[mt][nt][3],
                             af[mt][0], af[mt][1], af[mt][2], af[mt][3],
                             bf[nt][0], bf[nt][1]);
        }
        __syncthreads();
    }

    #pragma unroll
    for (int mt = 0; mt < 4; mt++) {
        const int mrow = m0 + wm * 64 + mt * 16 + gid;
        #pragma unroll
        for (int nt = 0; nt < 4; nt++) {
            const int ncol = n0 + wn * 32 + nt * 8 + tig * 2;
            const float bx = bias[ncol];
            const float by = bias[ncol + 1];
            float2 v0 = make_float2(acc[mt][nt][0] + bx, acc[mt][nt][1] + by);
            float2 v1 = make_float2(acc[mt][nt][2] + bx, acc[mt][nt][3] + by);
            *(float2*)(C + (long)mrow * DM + ncol) = v0;
            *(float2*)(C + (long)(mrow + 8) * DM + ncol) = v1;
        }
    }
}

// ---------------------------------------------------------------------------
// Tensor-core flash attention.
// CTA: 128 q-rows (8 warps x 16 rows), key tiles of 64. 256 threads.
// Q fragments persistent in registers (scale*log2e folded in).
// Smem: Ks[64][68] (B for QK^T), Vt[64][68] (V^T, B for PV), Ps[128][68]
// (Q staging, then per-warp P roundtrip). All padded stride 68 -> fragment
// LDS bank-index 4*gid+tig is unique per lane (conflict-free).
// ---------------------------------------------------------------------------
#define APAD 68
#define ATT_SMEM_U32 ((64 * APAD) * 2 + 128 * APAD)
#define ATT_SMEM_BYTES (ATT_SMEM_U32 * 4)

__global__ __launch_bounds__(256, 2) void attn_mma_kernel(
    const float* __restrict__ Q, const float* __restrict__ K,
    const float* __restrict__ V, float* __restrict__ Ctx)
{
    extern __shared__ uint32_t sm[];
    uint32_t* Ks = sm;                    // [64][APAD]
    uint32_t* Vt = Ks + 64 * APAD;        // [64][APAD]
    uint32_t* Ps = Vt + 64 * APAD;        // [128][APAD]

    const int bh = blockIdx.y;
    const int b  = bh >> 4;
    const int h  = bh & 15;
    const int q0 = blockIdx.x * 128;

    const int tid  = threadIdx.x;
    const int wid  = tid >> 5;
    const int lane = tid & 31;
    const int gid  = lane >> 2;
    const int tig  = lane & 3;
    const int r0   = wid * 16 + gid;   // this thread's first q-row (local)

    const float* Qg = Q + ((long)b * SEQ) * DM + h * DH;
    const float* Kg = K + ((long)b * SEQ) * DM + h * DH;
    const float* Vg = V + ((long)b * SEQ) * DM + h * DH;

    // ---- stage Q (scaled into log2 domain) into Ps, then grab A-fragments
    const float cf = 0.125f * 1.44269504088896f;   // 1/sqrt(64) * log2(e)
    {
        const int row  = tid >> 1;           // 0..127
        const int col0 = (tid & 1) * 32;
        const float4* qp = (const float4*)(Qg + (long)(q0 + row) * DM + col0);
        #pragma unroll
        for (int j = 0; j < 8; j++) {
            float4 v = qp[j];
            uint32_t* d = &Ps[row * APAD + col0 + j * 4];
            d[0] = rnd_tf32f(v.x * cf);
            d[1] = rnd_tf32f(v.y * cf);
            d[2] = rnd_tf32f(v.z * cf);
            d[3] = rnd_tf32f(v.w * cf);
        }
    }
    __syncthreads();

    uint32_t qf[8][4];
    #pragma unroll
    for (int ks = 0; ks < 8; ks++) {
        qf[ks][0] = Ps[r0 * APAD + ks * 8 + tig];
        qf[ks][1] = Ps[(r0 + 8) * APAD + ks * 8 + tig];
        qf[ks][2] = Ps[r0 * APAD + ks * 8 + tig + 4];
        qf[ks][3] = Ps[(r0 + 8) * APAD + ks * 8 + tig + 4];
    }

    float o[8][4];
    #pragma unroll
    for (int nt = 0; nt < 8; nt++)
        #pragma unroll
        for (int c = 0; c < 4; c++) o[nt][c] = 0.0f;
    float mr0 = -INFINITY, mr1 = -INFINITY, l0 = 0.0f, l1 = 0.0f;

    // global-load coords for K/V tiles
    const int krow = tid >> 2;          // 0..63
    const int kc   = (tid & 3) * 16;    // 0,16,32,48

    for (int kt = 0; kt < SEQ; kt += 64) {
        __syncthreads();   // prior-iter smem reads complete

        // load K tile -> Ks[key][dh] (tf32-rounded)
        {
            const float4* kp = (const float4*)(Kg + (long)(kt + krow) * DM + kc);
            const float4* vp = (const float4*)(Vg + (long)(kt + krow) * DM + kc);
            #pragma unroll
            for (int j = 0; j < 4; j++) {
                float4 kv = kp[j];
                uint32_t* d = &Ks[krow * APAD + kc + j * 4];
                d[0] = rnd_tf32f(kv.x); d[1] = rnd_tf32f(kv.y);
                d[2] = rnd_tf32f(kv.z); d[3] = rnd_tf32f(kv.w);
                float4 vv = vp[j];
                // transposed store: Vt[dh][key]
                Vt[(kc + j * 4 + 0) * APAD + krow] = rnd_tf32f(vv.x);
                Vt[(kc + j * 4 + 1) * APAD + krow] = rnd_tf32f(vv.y);
                Vt[(kc + j * 4 + 2) * APAD + krow] = rnd_tf32f(vv.z);
                Vt[(kc + j * 4 + 3) * APAD + krow] = rnd_tf32f(vv.w);
            }
        }
        __syncthreads();

        // S = Q * K^T  (per warp: 16 x 64)
        float s[8][4];
        #pragma unroll
        for (int nt = 0; nt < 8; nt++)
            #pragma unroll
            for (int c = 0; c < 4; c++) s[nt][c] = 0.0f;

        #pragma unroll
        for (int nt = 0; nt < 8; nt++) {
            const uint32_t* kb = &Ks[(nt * 8 + gid) * APAD];
            #pragma unroll
            for (int ks = 0; ks < 8; ks++) {
                uint32_t b0 = kb[ks * 8 + tig];
                uint32_t b1 = kb[ks * 8 + tig + 4];
                mma_tf32(s[nt][0], s[nt][1], s[nt][2], s[nt][3],
                         qf[ks][0], qf[ks][1], qf[ks][2], qf[ks][3], b0, b1);
            }
        }

        // online softmax (scores already in log2 domain)
        float mt0 = -INFINITY, mt1 = -INFINITY;
        #pragma unroll
        for (int nt = 0; nt < 8; nt++) {
            mt0 = fmaxf(mt0, fmaxf(s[nt][0], s[nt][1]));
            mt1 = fmaxf(mt1, fmaxf(s[nt][2], s[nt][3]));
        }
        mt0 = fmaxf(mt0, __shfl_xor_sync(0xffffffffu, mt0, 1));
        mt0 = fmaxf(mt0, __shfl_xor_sync(0xffffffffu, mt0, 2));
        mt1 = fmaxf(mt1, __shfl_xor_sync(0xffffffffu, mt1, 1));
        mt1 = fmaxf(mt1, __shfl_xor_sync(0xffffffffu, mt1, 2));

        const float mn0 = fmaxf(mr0, mt0);
        const float mn1 = fmaxf(mr1, mt1);
        const float a0 = ex2f(mr0 - mn0);
        const float a1 = ex2f(mr1 - mn1);
        mr0 = mn0; mr1 = mn1;

        __syncwarp();   // prior PV reads of Ps complete before overwrite

        float rs0 = 0.0f, rs1 = 0.0f;
        #pragma unroll
        for (int nt = 0; nt < 8; nt++) {
            float p0 = ex2f(s[nt][0] - mn0);
            float p1 = ex2f(s[nt][1] - mn0);
            float p2 = ex2f(s[nt][2] - mn1);
            float p3 = ex2f(s[nt][3] - mn1);
            rs0 += p0 + p1;
            rs1 += p2 + p3;
            uint2 w0 = make_uint2(rnd_tf32f(p0), rnd_tf32f(p1));
            uint2 w1 = make_uint2(rnd_tf32f(p2), rnd_tf32f(p3));
            *(uint2*)&Ps[r0 * APAD + nt * 8 + tig * 2] = w0;
            *(uint2*)&Ps[(r0 + 8) * APAD + nt * 8 + tig * 2] = w1;
        }
        rs0 += __shfl_xor_sync(0xffffffffu, rs0, 1);
        rs0 += __shfl_xor_sync(0xffffffffu, rs0, 2);
        rs1 += __shfl_xor_sync(0xffffffffu, rs1, 1);
        rs1 += __shfl_xor_sync(0xffffffffu, rs1, 2);

        l0 = l0 * a0 + rs0;
        l1 = l1 * a1 + rs1;
        #pragma unroll
        for (int nt = 0; nt < 8; nt++) {
            o[nt][0] *= a0; o[nt][1] *= a0;
            o[nt][2] *= a1; o[nt][3] *= a1;
        }
        __syncwarp();   // P stores visible to all lanes

        // O += P * V  (A = P rows of this warp, B = Vt)
        #pragma unroll
        for (int ks = 0; ks < 8; ks++) {
            uint32_t pa0 = Ps[r0 * APAD + ks * 8 + tig];
            uint32_t pa1 = Ps[(r0 + 8) * APAD + ks * 8 + tig];
            uint32_t pa2 = Ps[r0 * APAD + ks * 8 + tig + 4];
            uint32_t pa3 = Ps[(r0 + 8) * APAD + ks * 8 + tig + 4];
            #pragma unroll
            for (int nt = 0; nt < 8; nt++) {
                const uint32_t* vb = &Vt[(nt * 8 + gid) * APAD];
                uint32_t b0 = vb[ks * 8 + tig];
                uint32_t b1 = vb[ks * 8 + tig + 4];
                mma_tf32(o[nt][0], o[nt][1], o[nt][2], o[nt][3],
                         pa0, pa1, pa2, pa3, b0, b1);
            }
        }
    }

    // epilogue: normalize and write context
    const float inv0 = 1.0f / l0;
    const float inv1 = 1.0f / l1;
    float* C0 = Ctx + ((long)b * SEQ + q0 + r0) * DM + h * DH;
    float* C1 = Ctx + ((long)b * SEQ + q0 + r0 + 8) * DM + h * DH;
    #pragma unroll
    for (int nt = 0; nt < 8; nt++) {
        const int col = nt * 8 + tig * 2;
        *(float2*)(C0 + col) = make_float2(o[nt][0] * inv0, o[nt][1] * inv0);
        *(float2*)(C1 + col) = make_float2(o[nt][2] * inv1, o[nt][3] * inv1);
    }
}

// ---------------------------------------------------------------------------
// kernel_launch  — inputs: q,k,v, Wq,bq, Wk,bk, Wv,bv, Wo,bo
// ---------------------------------------------------------------------------
extern "C" void kernel_launch(void* const* d_in, const int* in_sizes, int n_in,
                              void* d_out, int out_size)
{
    const float* q  = (const float*)d_in[0];
    const float* k  = (const float*)d_in[1];
    const float* v  = (const float*)d_in[2];
    const float* Wq = (const float*)d_in[3];
    const float* bq = (const float*)d_in[4];
    const float* Wk = (const float*)d_in[5];
    const float* bk = (const float*)d_in[6];
    const float* Wv = (const float*)d_in[7];
    const float* bv = (const float*)d_in[8];
    const float* Wo = (const float*)d_in[9];
    const float* bo = (const float*)d_in[10];
    float* out = (float*)d_out;

    float *pQ, *pK, *pV, *pC;
    cudaGetSymbolAddress((void**)&pQ, g_Q);
    cudaGetSymbolAddress((void**)&pK, g_K);
    cudaGetSymbolAddress((void**)&pV, g_V);
    cudaGetSymbolAddress((void**)&pC, g_C);

    cudaFuncSetAttribute(attn_mma_kernel,
                         cudaFuncAttributeMaxDynamicSharedMemorySize,
                         ATT_SMEM_BYTES);

    dim3 ggrid(DM / BN, MROWS / BM);     // (8, 32)
    gemm_tf32_kernel<<<ggrid, 256>>>(q, Wq, bq, pQ);
    gemm_tf32_kernel<<<ggrid, 256>>>(k, Wk, bk, pK);
    gemm_tf32_kernel<<<ggrid, 256>>>(v, Wv, bv, pV);

    dim3 agrid(SEQ / 128, BATCH * NH);   // (16, 32)
    attn_mma_kernel<<<agrid, 256, ATT_SMEM_BYTES>>>(pQ, pK, pV, pC);

    gemm_tf32_kernel<<<ggrid, 256>>>(pC, Wo, bo, out);
}